// round 8
// baseline (speedup 1.0000x reference)
#include <cuda_runtime.h>
#include <cuda_fp16.h>
#include <cstdint>
#include <cstddef>

// Problem constants
#define BB 2
#define CC 256
#define NN 4096
#define HH 8
#define HD 32
#define TC 768   // 3*C

// 1/sqrt(32) * log2(e): fold softmax scale + exp2 conversion into Q
__device__ __constant__ float QSCALE_C = 0.17677669529663687f * 1.4426950408889634f;

#define ONES2 0x3C003C00u   // half2(1.0, 1.0)

// -------- scratch (static device globals; no allocation) --------
__device__ __align__(128) __half g_xT  [(size_t)BB * NN * CC];   // [b][n][c]
__device__ __align__(128) __half g_wqkv[(size_t)TC * CC];        // [o][c]
__device__ __align__(128) __half g_wout[(size_t)CC * CC];        // [o][c]
__device__ __align__(128) __half g_Q   [(size_t)BB * HH * NN * HD]; // [b][h][n][d] (pre-scaled)
__device__ __align__(128) __half g_K   [(size_t)BB * HH * NN * HD]; // [b][h][n][d]
__device__ __align__(128) __half g_V   [(size_t)BB * HH * HD * NN]; // [b][h][d][n]
__device__ __align__(128) __half g_AO  [(size_t)BB * NN * CC];   // [b][n][c]

// -------- mma.sync m16n8k16 f16 -> f32 --------
__device__ __forceinline__ void mma16816(float* c, const uint32_t* a, uint32_t b0, uint32_t b1) {
    asm volatile(
        "mma.sync.aligned.m16n8k16.row.col.f32.f16.f16.f32 "
        "{%0,%1,%2,%3}, {%4,%5,%6,%7}, {%8,%9}, {%0,%1,%2,%3};\n"
        : "+f"(c[0]), "+f"(c[1]), "+f"(c[2]), "+f"(c[3])
        : "r"(a[0]), "r"(a[1]), "r"(a[2]), "r"(a[3]), "r"(b0), "r"(b1));
}

__device__ __forceinline__ uint32_t ld_u32s(const __half* p) {
    return *reinterpret_cast<const uint32_t*>(p);
}

__device__ __forceinline__ void ldsm_x4(uint32_t& r0, uint32_t& r1, uint32_t& r2, uint32_t& r3,
                                        const __half* p) {
    uint32_t a = (uint32_t)__cvta_generic_to_shared(p);
    asm volatile("ldmatrix.sync.aligned.m8n8.x4.shared.b16 {%0,%1,%2,%3}, [%4];\n"
                 : "=r"(r0), "=r"(r1), "=r"(r2), "=r"(r3) : "r"(a));
}

__device__ __forceinline__ float ex2f(float x) {
    float y;
    asm("ex2.approx.f32 %0, %1;\n" : "=f"(y) : "f"(x));
    return y;
}

__device__ __forceinline__ uint32_t h2ex2(uint32_t x) {
    uint32_t y;
    asm("ex2.approx.f16x2 %0, %1;\n" : "=r"(y) : "r"(x));
    return y;
}

__device__ __forceinline__ uint32_t pack_h2(float lo, float hi) {
    __half2 t = __floats2half2_rn(lo, hi);
    return *reinterpret_cast<uint32_t*>(&t);
}

__device__ __forceinline__ void cp16u(uint32_t dst, const void* src) {
    asm volatile("cp.async.cg.shared.global [%0], [%1], 16;\n" :: "r"(dst), "l"(src));
}
#define CP_COMMIT asm volatile("cp.async.commit_group;\n" ::: "memory")
#define CP_WAIT0  asm volatile("cp.async.wait_group 0;\n" ::: "memory")

// -------- kernel 1: convert weights to fp16 --------
__global__ void conv_weights(const float* __restrict__ wqkv, const float* __restrict__ wout) {
    int i = blockIdx.x * 256 + threadIdx.x;
    if (i < TC * CC) g_wqkv[i] = __float2half_rn(wqkv[i]);
    if (i < CC * CC) g_wout[i] = __float2half_rn(wout[i]);
}

// -------- kernel 2: transpose x [b][c][n] f32 -> xT [b][n][c] f16 --------
__global__ void transpose_x(const float* __restrict__ x) {
    __shared__ float t[32][33];
    int b  = blockIdx.z;
    int n0 = blockIdx.x * 32;
    int c0 = blockIdx.y * 32;
    int tx = threadIdx.x, ty = threadIdx.y;
#pragma unroll
    for (int j = 0; j < 32; j += 8)
        t[ty + j][tx] = x[((size_t)b * CC + (c0 + ty + j)) * NN + n0 + tx];
    __syncthreads();
#pragma unroll
    for (int j = 0; j < 32; j += 8)
        g_xT[((size_t)b * NN + (n0 + ty + j)) * CC + c0 + tx] = __float2half_rn(t[tx][ty + j]);
}

// -------- kernel 3/5: NT GEMM out[o][n] = sum_c A[o][c] * Bx[n][c] + bias[o] --------
template <int MODE>
__global__ void __launch_bounds__(128) gemm_nt(const float* __restrict__ bias,
                                              float* __restrict__ outF) {
    __shared__ __half As[64][40];
    __shared__ __half Bs[64][40];

    const int b  = blockIdx.z;
    const int n0 = blockIdx.x * 64;
    const int o0 = blockIdx.y * 64;
    const int tid   = threadIdx.x;
    const int warp  = tid >> 5;
    const int lane  = tid & 31;
    const int warpM = warp >> 1;
    const int warpN = warp & 1;
    const int lr = lane >> 2;
    const int lc = (lane & 3) * 2;

    const __half* Aw = (MODE == 0) ? g_wqkv : g_wout;
    const __half* Bx = ((MODE == 0) ? g_xT : g_AO) + (size_t)b * NN * CC;

    float acc[2][4][4];
#pragma unroll
    for (int mt = 0; mt < 2; mt++)
#pragma unroll
        for (int nt = 0; nt < 4; nt++)
#pragma unroll
            for (int j = 0; j < 4; j++) acc[mt][nt][j] = 0.f;

    for (int kk0 = 0; kk0 < CC; kk0 += 32) {
#pragma unroll
        for (int i = tid; i < 256; i += 128) {
            int row = i >> 2, seg = i & 3;
            *reinterpret_cast<uint4*>(&As[row][seg * 8]) =
                *reinterpret_cast<const uint4*>(&Aw[(size_t)(o0 + row) * CC + kk0 + seg * 8]);
            *reinterpret_cast<uint4*>(&Bs[row][seg * 8]) =
                *reinterpret_cast<const uint4*>(&Bx[(size_t)(n0 + row) * CC + kk0 + seg * 8]);
        }
        __syncthreads();
#pragma unroll
        for (int ks = 0; ks < 2; ks++) {
            uint32_t a[2][4];
#pragma unroll
            for (int mt = 0; mt < 2; mt++) {
                int r = warpM * 32 + mt * 16 + lr;
                a[mt][0] = ld_u32s(&As[r    ][ks * 16 + lc    ]);
                a[mt][1] = ld_u32s(&As[r + 8][ks * 16 + lc    ]);
                a[mt][2] = ld_u32s(&As[r    ][ks * 16 + lc + 8]);
                a[mt][3] = ld_u32s(&As[r + 8][ks * 16 + lc + 8]);
            }
            uint32_t bf[4][2];
#pragma unroll
            for (int nt = 0; nt < 4; nt++) {
                int c = warpN * 32 + nt * 8 + lr;
                bf[nt][0] = ld_u32s(&Bs[c][ks * 16 + lc    ]);
                bf[nt][1] = ld_u32s(&Bs[c][ks * 16 + lc + 8]);
            }
#pragma unroll
            for (int mt = 0; mt < 2; mt++)
#pragma unroll
                for (int nt = 0; nt < 4; nt++)
                    mma16816(acc[mt][nt], a[mt], bf[nt][0], bf[nt][1]);
        }
        __syncthreads();
    }

    const float qs = QSCALE_C;
#pragma unroll
    for (int mt = 0; mt < 2; mt++) {
#pragma unroll
        for (int nt = 0; nt < 4; nt++) {
#pragma unroll
            for (int j = 0; j < 4; j++) {
                int r_loc = warpM * 32 + mt * 16 + lr + ((j >> 1) ? 8 : 0);
                int c_loc = warpN * 32 + nt * 8 + lc + (j & 1);
                int o = o0 + r_loc;
                int n = n0 + c_loc;
                float v = acc[mt][nt][j] + bias[o];
                if (MODE == 0) {
                    if (o < CC) {
                        int h = o >> 5, d = o & 31;
                        g_Q[(((size_t)b * HH + h) * NN + n) * HD + d] = __float2half_rn(v * qs);
                    } else if (o < 2 * CC) {
                        int o2 = o - CC;
                        int h = o2 >> 5, d = o2 & 31;
                        g_K[(((size_t)b * HH + h) * NN + n) * HD + d] = __float2half_rn(v);
                    } else {
                        int o2 = o - 2 * CC;
                        int h = o2 >> 5, d = o2 & 31;
                        g_V[(((size_t)b * HH + h) * HD + d) * NN + n] = __float2half_rn(v);
                    }
                } else {
                    outF[((size_t)b * CC + o) * NN + n] = v;
                }
            }
        }
    }
}

// -------- kernel 4: flash attention --------
// 64 q-rows / 128 threads / 4 warps, single barrier per tile, max-unchanged
// fast path, hoisted prefetch addressing, forced occupancy 6 CTAs/SM.
// grid (N/64, H, B).
#define KBUF_BYTES (64 * 40 * 2)   // 5120
#define VBUF_BYTES (32 * 72 * 2)   // 4608

__global__ void __launch_bounds__(128, 6) flash_attn() {
    __shared__ __half Ks[2][64][40];   // [buf][key][d]  80B rows: LDSM conflict-free
    __shared__ __half Vs[2][32][72];   // [buf][d][key]  144B rows: LDSM conflict-free

    const int b  = blockIdx.z;
    const int h  = blockIdx.y;
    const int q0 = blockIdx.x * 64;
    const int tid  = threadIdx.x;
    const int warp = tid >> 5;
    const int lane = tid & 31;
    const int lr = lane >> 2;
    const int lc = (lane & 3) * 2;
    // ldmatrix lane grouping
    const int lg  = lane >> 3;
    const int lrr = lane & 7;
    const int rowoff = ((lg >> 1) ? 8 : 0) + lrr;
    const int coloff = (lg & 1) * 8;

    const __half* Qb = g_Q + (((size_t)b * HH + h) * NN) * HD;
    const __half* Kb = g_K + (((size_t)b * HH + h) * NN) * HD;
    const __half* Vb = g_V + (((size_t)b * HH + h) * HD) * NN;

    const int qrow = q0 + warp * 16 + lr;

    // Q fragments (registers, whole kernel)
    uint32_t qa[2][4];
#pragma unroll
    for (int ks = 0; ks < 2; ks++) {
        qa[ks][0] = ld_u32s(&Qb[(size_t)(qrow    ) * HD + ks * 16 + lc    ]);
        qa[ks][1] = ld_u32s(&Qb[(size_t)(qrow + 8) * HD + ks * 16 + lc    ]);
        qa[ks][2] = ld_u32s(&Qb[(size_t)(qrow    ) * HD + ks * 16 + lc + 8]);
        qa[ks][3] = ld_u32s(&Qb[(size_t)(qrow + 8) * HD + ks * 16 + lc + 8]);
    }

    float m0 = -1e30f, m1 = -1e30f;
    float o[4][4];
    float lacc[4];
#pragma unroll
    for (int dt = 0; dt < 4; dt++)
#pragma unroll
        for (int j = 0; j < 4; j++) o[dt][j] = 0.f;
#pragma unroll
    for (int j = 0; j < 4; j++) lacc[j] = 0.f;

    // ---- hoisted prefetch addressing ----
    // K: 64 rows x 4 chunks of 16B; thread covers (tid) and (tid+128)
    // V: 32 rows x 8 chunks of 16B; same two slots
    const int t2 = tid + 128;
    const __half* kp0 = Kb + (size_t)(tid >> 2) * HD + (tid & 3) * 8;
    const __half* kp1 = Kb + (size_t)(t2  >> 2) * HD + (t2  & 3) * 8;
    const __half* vp0 = Vb + (size_t)(tid >> 3) * NN + (tid & 7) * 8;
    const __half* vp1 = Vb + (size_t)(t2  >> 3) * NN + (t2  & 7) * 8;
    const uint32_t kd0 = (uint32_t)__cvta_generic_to_shared(&Ks[0][tid >> 2][(tid & 3) * 8]);
    const uint32_t kd1 = (uint32_t)__cvta_generic_to_shared(&Ks[0][t2  >> 2][(t2  & 3) * 8]);
    const uint32_t vd0 = (uint32_t)__cvta_generic_to_shared(&Vs[0][tid >> 3][(tid & 7) * 8]);
    const uint32_t vd1 = (uint32_t)__cvta_generic_to_shared(&Vs[0][t2  >> 3][(t2  & 7) * 8]);

    // issue prefetch into buffer bf and advance source pointers by one tile
    auto prefetch = [&](int bf) {
        const uint32_t kofs = bf ? KBUF_BYTES : 0;
        const uint32_t vofs = bf ? VBUF_BYTES : 0;
        cp16u(kd0 + kofs, kp0);
        cp16u(kd1 + kofs, kp1);
        cp16u(vd0 + vofs, vp0);
        cp16u(vd1 + vofs, vp1);
        kp0 += 64 * HD; kp1 += 64 * HD;
        vp0 += 64;      vp1 += 64;
    };

    const int NT = NN / 64;
    prefetch(0);
    CP_COMMIT;

    for (int kt = 0; kt < NT; kt++) {
        const int bf = kt & 1;
        CP_WAIT0;              // buffer bf fully staged (only group outstanding)
        __syncthreads();       // all copies visible; all warps done reading bf^1
        if (kt + 1 < NT) {
            prefetch(bf ^ 1);  // overlaps with compute below
            CP_COMMIT;
        }

        // S = Q K^T  (16 x 64 per warp)
        float s[8][4];
#pragma unroll
        for (int nt = 0; nt < 8; nt++)
#pragma unroll
            for (int j = 0; j < 4; j++) s[nt][j] = 0.f;
#pragma unroll
        for (int ks = 0; ks < 2; ks++) {
#pragma unroll
            for (int ntp = 0; ntp < 4; ntp++) {
                uint32_t k0, k1, k2, k3;
                ldsm_x4(k0, k1, k2, k3, &Ks[bf][16 * ntp + rowoff][ks * 16 + coloff]);
                mma16816(s[2 * ntp    ], qa[ks], k0, k1);
                mma16816(s[2 * ntp + 1], qa[ks], k2, k3);
            }
        }

        // row max (scores already in exp2 domain)
        float mn0 = m0, mn1 = m1;
#pragma unroll
        for (int nt = 0; nt < 8; nt++) {
            mn0 = fmaxf(mn0, fmaxf(s[nt][0], s[nt][1]));
            mn1 = fmaxf(mn1, fmaxf(s[nt][2], s[nt][3]));
        }
#pragma unroll
        for (int off = 1; off < 4; off <<= 1) {
            mn0 = fmaxf(mn0, __shfl_xor_sync(0xffffffffu, mn0, off));
            mn1 = fmaxf(mn1, __shfl_xor_sync(0xffffffffu, mn1, off));
        }

        // fast path: max unchanged for every row in warp -> a0=a1=1, skip rescale
        if (!__all_sync(0xffffffffu, (mn0 == m0) & (mn1 == m1))) {
            const float a0 = ex2f(m0 - mn0);
            const float a1 = ex2f(m1 - mn1);
            m0 = mn0; m1 = mn1;
#pragma unroll
            for (int dt = 0; dt < 4; dt++) {
                o[dt][0] *= a0; o[dt][1] *= a0;
                o[dt][2] *= a1; o[dt][3] *= a1;
            }
            lacc[0] *= a0; lacc[1] *= a0; lacc[2] *= a1; lacc[3] *= a1;
        }

        // P = exp2(S - m) in half2 (packed MUFU == A-frag repack)
        uint32_t ph[8][2];
#pragma unroll
        for (int nt = 0; nt < 8; nt++) {
            ph[nt][0] = h2ex2(pack_h2(s[nt][0] - m0, s[nt][1] - m0));
            ph[nt][1] = h2ex2(pack_h2(s[nt][2] - m1, s[nt][3] - m1));
        }

        // O += P V ; l += P @ ones
#pragma unroll
        for (int kk = 0; kk < 4; kk++) {
            uint32_t pa[4];
            pa[0] = ph[2 * kk    ][0];
            pa[1] = ph[2 * kk    ][1];
            pa[2] = ph[2 * kk + 1][0];
            pa[3] = ph[2 * kk + 1][1];
            mma16816(lacc, pa, ONES2, ONES2);
#pragma unroll
            for (int dtp = 0; dtp < 2; dtp++) {
                uint32_t v0, v1, v2, v3;
                ldsm_x4(v0, v1, v2, v3, &Vs[bf][16 * dtp + rowoff][kk * 16 + coloff]);
                mma16816(o[2 * dtp    ], pa, v0, v1);
                mma16816(o[2 * dtp + 1], pa, v2, v3);
            }
        }
    }

    // normalize and write AO [b][n][c] fp16
    const float il0 = 1.f / lacc[0];
    const float il1 = 1.f / lacc[2];
#pragma unroll
    for (int dt = 0; dt < 4; dt++) {
#pragma unroll
        for (int j = 0; j < 4; j++) {
            int r = qrow + ((j >> 1) ? 8 : 0);
            int d = dt * 8 + lc + (j & 1);
            float v = o[dt][j] * ((j < 2) ? il0 : il1);
            g_AO[((size_t)b * NN + r) * CC + h * HD + d] = __float2half_rn(v);
        }
    }
}

// -------- launch --------
extern "C" void kernel_launch(void* const* d_in, const int* in_sizes, int n_in,
                              void* d_out, int out_size) {
    const float* x      = (const float*)d_in[0];
    const float* qkv_w  = (const float*)d_in[1];
    const float* qkv_b  = (const float*)d_in[2];
    const float* out_w  = (const float*)d_in[3];
    const float* out_b  = (const float*)d_in[4];
    float* out = (float*)d_out;

    conv_weights<<<TC * CC / 256, 256>>>(qkv_w, out_w);

    dim3 tgrid(NN / 32, CC / 32, BB);
    transpose_x<<<tgrid, dim3(32, 8)>>>(x);

    dim3 g0(NN / 64, TC / 64, BB);
    gemm_nt<0><<<g0, 128>>>(qkv_b, nullptr);

    dim3 gf(NN / 64, HH, BB);
    flash_attn<<<gf, 128>>>();

    dim3 g1(NN / 64, CC / 64, BB);
    gemm_nt<1><<<g1, 128>>>(out_b, out);
}

// round 11
// speedup vs baseline: 1.0005x; 1.0005x over previous
#include <cuda_runtime.h>
#include <cuda_fp16.h>
#include <cstdint>
#include <cstddef>

// Problem constants
#define BB 2
#define CC 256
#define NN 4096
#define HH 8
#define HD 32
#define TC 768   // 3*C

// 1/sqrt(32) * log2(e): fold softmax scale + exp2 conversion into Q
__device__ __constant__ float QSCALE_C = 0.17677669529663687f * 1.4426950408889634f;

#define ONES2 0x3C003C00u   // half2(1.0, 1.0)

// -------- scratch (static device globals; no allocation) --------
__device__ __align__(128) __half g_wqkv[(size_t)TC * CC];        // [o][c]
__device__ __align__(128) __half g_wout[(size_t)CC * CC];        // [o][c]
__device__ __align__(128) __half g_Q   [(size_t)BB * HH * NN * HD]; // [b][h][n][d] (pre-scaled)
__device__ __align__(128) __half g_K   [(size_t)BB * HH * NN * HD]; // [b][h][n][d]
__device__ __align__(128) __half g_V   [(size_t)BB * HH * HD * NN]; // [b][h][d][n]
__device__ __align__(128) __half g_AO  [(size_t)BB * NN * CC];   // [b][n][c]

// -------- mma.sync m16n8k16 f16 -> f32 --------
__device__ __forceinline__ void mma16816(float* c, const uint32_t* a, uint32_t b0, uint32_t b1) {
    asm volatile(
        "mma.sync.aligned.m16n8k16.row.col.f32.f16.f16.f32 "
        "{%0,%1,%2,%3}, {%4,%5,%6,%7}, {%8,%9}, {%0,%1,%2,%3};\n"
        : "+f"(c[0]), "+f"(c[1]), "+f"(c[2]), "+f"(c[3])
        : "r"(a[0]), "r"(a[1]), "r"(a[2]), "r"(a[3]), "r"(b0), "r"(b1));
}

__device__ __forceinline__ uint32_t ld_u32s(const __half* p) {
    return *reinterpret_cast<const uint32_t*>(p);
}

__device__ __forceinline__ void ldsm_x4(uint32_t& r0, uint32_t& r1, uint32_t& r2, uint32_t& r3,
                                        const __half* p) {
    uint32_t a = (uint32_t)__cvta_generic_to_shared(p);
    asm volatile("ldmatrix.sync.aligned.m8n8.x4.shared.b16 {%0,%1,%2,%3}, [%4];\n"
                 : "=r"(r0), "=r"(r1), "=r"(r2), "=r"(r3) : "r"(a));
}

__device__ __forceinline__ void ldsm_x4t(uint32_t& r0, uint32_t& r1, uint32_t& r2, uint32_t& r3,
                                         const __half* p) {
    uint32_t a = (uint32_t)__cvta_generic_to_shared(p);
    asm volatile("ldmatrix.sync.aligned.m8n8.x4.trans.shared.b16 {%0,%1,%2,%3}, [%4];\n"
                 : "=r"(r0), "=r"(r1), "=r"(r2), "=r"(r3) : "r"(a));
}

__device__ __forceinline__ float ex2f(float x) {
    float y;
    asm("ex2.approx.f32 %0, %1;\n" : "=f"(y) : "f"(x));
    return y;
}

__device__ __forceinline__ uint32_t h2ex2(uint32_t x) {
    uint32_t y;
    asm("ex2.approx.f16x2 %0, %1;\n" : "=r"(y) : "r"(x));
    return y;
}

__device__ __forceinline__ uint32_t pack_h2(float lo, float hi) {
    __half2 t = __floats2half2_rn(lo, hi);
    return *reinterpret_cast<uint32_t*>(&t);
}

__device__ __forceinline__ void cp16(void* dst, const void* src) {
    uint32_t d = (uint32_t)__cvta_generic_to_shared(dst);
    asm volatile("cp.async.cg.shared.global [%0], [%1], 16;\n" :: "r"(d), "l"(src));
}
#define CP_COMMIT asm volatile("cp.async.commit_group;\n" ::: "memory")
#define CP_WAIT0  asm volatile("cp.async.wait_group 0;\n" ::: "memory")

// -------- kernel 1: convert weights to fp16 --------
__global__ void conv_weights(const float* __restrict__ wqkv, const float* __restrict__ wout) {
    int i = blockIdx.x * 256 + threadIdx.x;
    if (i < TC * CC) g_wqkv[i] = __float2half_rn(wqkv[i]);
    if (i < CC * CC) g_wout[i] = __float2half_rn(wout[i]);
}

// -------- kernel 2/4: NT GEMM out[o][n] = sum_c A[o][c] * B[...] + bias[o] --------
// MODE 0: A = g_wqkv (M=768), B = x (f32, [c][n] layout; transpose fused into
//         staging + ldmatrix.trans); epilogue scatters into Q (scaled), K, V.
// MODE 1: A = g_wout (M=256), B = g_AO (f16, [n][c]); epilogue -> fp32 d_out.
template <int MODE>
__global__ void __launch_bounds__(128) gemm_nt(const float* __restrict__ xin,
                                               const float* __restrict__ bias,
                                               float* __restrict__ outF) {
    __shared__ __half As[64][40];
    __shared__ __half Bs[64][40];          // MODE 1 layout [n 64][c 32+pad]
    __half (*Bs2)[72] = reinterpret_cast<__half (*)[72]>(&Bs[0][0]);  // MODE 0 layout [c 32][n 64+pad]

    const int b  = blockIdx.z;
    const int n0 = blockIdx.x * 64;
    const int o0 = blockIdx.y * 64;
    const int tid   = threadIdx.x;
    const int warp  = tid >> 5;
    const int lane  = tid & 31;
    const int warpM = warp >> 1;
    const int warpN = warp & 1;
    const int lr = lane >> 2;
    const int lc = (lane & 3) * 2;
    // ldmatrix lane grouping
    const int lg  = lane >> 3;
    const int lrr = lane & 7;
    const int browoff = (lg & 1) * 8 + lrr;   // MODE 0: k-row within 16-k step
    const int bcoloff = (lg >> 1) * 8;        // MODE 0: +8 n for matrices 2,3

    const __half* Aw  = (MODE == 0) ? g_wqkv : g_wout;
    const __half* BxH = (MODE == 0) ? nullptr : g_AO + (size_t)b * NN * CC;
    const float*  BxF = (MODE == 0) ? xin + (size_t)b * CC * NN : nullptr;

    float acc[2][4][4];
#pragma unroll
    for (int mt = 0; mt < 2; mt++)
#pragma unroll
        for (int nt = 0; nt < 4; nt++)
#pragma unroll
            for (int j = 0; j < 4; j++) acc[mt][nt][j] = 0.f;

    for (int kk0 = 0; kk0 < CC; kk0 += 32) {
        // stage A [64 o][32 c]: 64 rows x 4 chunks of 16B (256 slots, 2/thread)
#pragma unroll
        for (int i = tid; i < 256; i += 128) {
            int row = i >> 2, seg = i & 3;
            *reinterpret_cast<uint4*>(&As[row][seg * 8]) =
                *reinterpret_cast<const uint4*>(&Aw[(size_t)(o0 + row) * CC + kk0 + seg * 8]);
        }

        if (MODE == 0) {
            // stage B: x f32 [c][n] -> Bs2 [32 c][64 n] f16 (coalesced along n)
            int crow = tid >> 2;            // 0..31
            int seg  = tid & 3;             // 4 segments of 16 floats
            const float* src = &BxF[(size_t)(kk0 + crow) * NN + n0 + seg * 16];
            __half* dst = &Bs2[crow][seg * 16];
#pragma unroll
            for (int q = 0; q < 4; q++) {
                float4 f = *reinterpret_cast<const float4*>(src + q * 4);
                *reinterpret_cast<__half2*>(dst + q * 4)     = __floats2half2_rn(f.x, f.y);
                *reinterpret_cast<__half2*>(dst + q * 4 + 2) = __floats2half2_rn(f.z, f.w);
            }
        } else {
            // stage B: g_AO f16 [n][c] -> Bs [64 n][32 c]: 256 slots, 2/thread
#pragma unroll
            for (int i = tid; i < 256; i += 128) {
                int row = i >> 2, seg = i & 3;
                *reinterpret_cast<uint4*>(&Bs[row][seg * 8]) =
                    *reinterpret_cast<const uint4*>(&BxH[(size_t)(n0 + row) * CC + kk0 + seg * 8]);
            }
        }
        __syncthreads();

#pragma unroll
        for (int ks = 0; ks < 2; ks++) {
            uint32_t a[2][4];
#pragma unroll
            for (int mt = 0; mt < 2; mt++) {
                int r = warpM * 32 + mt * 16 + lr;
                a[mt][0] = ld_u32s(&As[r    ][ks * 16 + lc    ]);
                a[mt][1] = ld_u32s(&As[r + 8][ks * 16 + lc    ]);
                a[mt][2] = ld_u32s(&As[r    ][ks * 16 + lc + 8]);
                a[mt][3] = ld_u32s(&As[r + 8][ks * 16 + lc + 8]);
            }
            if (MODE == 0) {
#pragma unroll
                for (int ntp = 0; ntp < 2; ntp++) {
                    // ldmatrix.x4.trans from [k][n]: r0,r1 = (k0-7, k8-15) at
                    // n-tile base; r2,r3 same at +8 n.
                    uint32_t b0, b1, b2, b3;
                    ldsm_x4t(b0, b1, b2, b3,
                             &Bs2[ks * 16 + browoff][warpN * 32 + ntp * 16 + bcoloff]);
#pragma unroll
                    for (int mt = 0; mt < 2; mt++) {
                        mma16816(acc[mt][2 * ntp    ], a[mt], b0, b1);
                        mma16816(acc[mt][2 * ntp + 1], a[mt], b2, b3);
                    }
                }
            } else {
                uint32_t bf[4][2];
#pragma unroll
                for (int nt = 0; nt < 4; nt++) {
                    int c = warpN * 32 + nt * 8 + lr;
                    bf[nt][0] = ld_u32s(&Bs[c][ks * 16 + lc    ]);
                    bf[nt][1] = ld_u32s(&Bs[c][ks * 16 + lc + 8]);
                }
#pragma unroll
                for (int mt = 0; mt < 2; mt++)
#pragma unroll
                    for (int nt = 0; nt < 4; nt++)
                        mma16816(acc[mt][nt], a[mt], bf[nt][0], bf[nt][1]);
            }
        }
        __syncthreads();
    }

    const float qs = QSCALE_C;
#pragma unroll
    for (int mt = 0; mt < 2; mt++) {
#pragma unroll
        for (int nt = 0; nt < 4; nt++) {
#pragma unroll
            for (int j = 0; j < 4; j++) {
                int r_loc = warpM * 32 + mt * 16 + lr + ((j >> 1) ? 8 : 0);
                int c_loc = warpN * 32 + nt * 8 + lc + (j & 1);
                int o = o0 + r_loc;
                int n = n0 + c_loc;
                float v = acc[mt][nt][j] + bias[o];
                if (MODE == 0) {
                    if (o < CC) {
                        int h = o >> 5, d = o & 31;
                        g_Q[(((size_t)b * HH + h) * NN + n) * HD + d] = __float2half_rn(v * qs);
                    } else if (o < 2 * CC) {
                        int o2 = o - CC;
                        int h = o2 >> 5, d = o2 & 31;
                        g_K[(((size_t)b * HH + h) * NN + n) * HD + d] = __float2half_rn(v);
                    } else {
                        int o2 = o - 2 * CC;
                        int h = o2 >> 5, d = o2 & 31;
                        g_V[(((size_t)b * HH + h) * HD + d) * NN + n] = __float2half_rn(v);
                    }
                } else {
                    outF[((size_t)b * CC + o) * NN + n] = v;
                }
            }
        }
    }
}

// -------- kernel 3: flash attention (exact R6 config — best measured) --------
__global__ void __launch_bounds__(128) flash_attn() {
    __shared__ __half Ks[2][64][40];   // [buf][key][d]  80B rows: LDSM conflict-free
    __shared__ __half Vs[2][32][72];   // [buf][d][key]  144B rows: LDSM conflict-free

    const int b  = blockIdx.z;
    const int h  = blockIdx.y;
    const int q0 = blockIdx.x * 64;
    const int tid  = threadIdx.x;
    const int warp = tid >> 5;
    const int lane = tid & 31;
    const int lr = lane >> 2;
    const int lc = (lane & 3) * 2;
    const int lg  = lane >> 3;
    const int lrr = lane & 7;
    const int rowoff = ((lg >> 1) ? 8 : 0) + lrr;
    const int coloff = (lg & 1) * 8;

    const __half* Qb = g_Q + (((size_t)b * HH + h) * NN) * HD;
    const __half* Kb = g_K + (((size_t)b * HH + h) * NN) * HD;
    const __half* Vb = g_V + (((size_t)b * HH + h) * HD) * NN;

    const int qrow = q0 + warp * 16 + lr;

    uint32_t qa[2][4];
#pragma unroll
    for (int ks = 0; ks < 2; ks++) {
        qa[ks][0] = ld_u32s(&Qb[(size_t)(qrow    ) * HD + ks * 16 + lc    ]);
        qa[ks][1] = ld_u32s(&Qb[(size_t)(qrow + 8) * HD + ks * 16 + lc    ]);
        qa[ks][2] = ld_u32s(&Qb[(size_t)(qrow    ) * HD + ks * 16 + lc + 8]);
        qa[ks][3] = ld_u32s(&Qb[(size_t)(qrow + 8) * HD + ks * 16 + lc + 8]);
    }

    float m0 = -1e30f, m1 = -1e30f;
    float o[4][4];
    float lacc[4];
#pragma unroll
    for (int dt = 0; dt < 4; dt++)
#pragma unroll
        for (int j = 0; j < 4; j++) o[dt][j] = 0.f;
#pragma unroll
    for (int j = 0; j < 4; j++) lacc[j] = 0.f;

    auto prefetch = [&](int kt, int bf) {
        const int kn0 = kt * 64;
#pragma unroll
        for (int j = 0; j < 2; j++) {
            int c = tid + j * 128;
            int krow = c >> 2, kseg = c & 3;
            cp16(&Ks[bf][krow][kseg * 8], &Kb[(size_t)(kn0 + krow) * HD + kseg * 8]);
            int vrow = c >> 3, vseg = c & 7;
            cp16(&Vs[bf][vrow][vseg * 8], &Vb[(size_t)vrow * NN + kn0 + vseg * 8]);
        }
    };

    const int NT = NN / 64;
    prefetch(0, 0);
    CP_COMMIT;

    for (int kt = 0; kt < NT; kt++) {
        const int bf = kt & 1;
        CP_WAIT0;
        __syncthreads();
        if (kt + 1 < NT) {
            prefetch(kt + 1, bf ^ 1);
            CP_COMMIT;
        }

        float s[8][4];
#pragma unroll
        for (int nt = 0; nt < 8; nt++)
#pragma unroll
            for (int j = 0; j < 4; j++) s[nt][j] = 0.f;
#pragma unroll
        for (int ks = 0; ks < 2; ks++) {
#pragma unroll
            for (int ntp = 0; ntp < 4; ntp++) {
                uint32_t k0, k1, k2, k3;
                ldsm_x4(k0, k1, k2, k3, &Ks[bf][16 * ntp + rowoff][ks * 16 + coloff]);
                mma16816(s[2 * ntp    ], qa[ks], k0, k1);
                mma16816(s[2 * ntp + 1], qa[ks], k2, k3);
            }
        }

        float mn0 = m0, mn1 = m1;
#pragma unroll
        for (int nt = 0; nt < 8; nt++) {
            mn0 = fmaxf(mn0, fmaxf(s[nt][0], s[nt][1]));
            mn1 = fmaxf(mn1, fmaxf(s[nt][2], s[nt][3]));
        }
#pragma unroll
        for (int off = 1; off < 4; off <<= 1) {
            mn0 = fmaxf(mn0, __shfl_xor_sync(0xffffffffu, mn0, off));
            mn1 = fmaxf(mn1, __shfl_xor_sync(0xffffffffu, mn1, off));
        }

        if (!__all_sync(0xffffffffu, (mn0 == m0) & (mn1 == m1))) {
            const float a0 = ex2f(m0 - mn0);
            const float a1 = ex2f(m1 - mn1);
            m0 = mn0; m1 = mn1;
#pragma unroll
            for (int dt = 0; dt < 4; dt++) {
                o[dt][0] *= a0; o[dt][1] *= a0;
                o[dt][2] *= a1; o[dt][3] *= a1;
            }
            lacc[0] *= a0; lacc[1] *= a0; lacc[2] *= a1; lacc[3] *= a1;
        }

        uint32_t ph[8][2];
#pragma unroll
        for (int nt = 0; nt < 8; nt++) {
            ph[nt][0] = h2ex2(pack_h2(s[nt][0] - m0, s[nt][1] - m0));
            ph[nt][1] = h2ex2(pack_h2(s[nt][2] - m1, s[nt][3] - m1));
        }

#pragma unroll
        for (int kk = 0; kk < 4; kk++) {
            uint32_t pa[4];
            pa[0] = ph[2 * kk    ][0];
            pa[1] = ph[2 * kk    ][1];
            pa[2] = ph[2 * kk + 1][0];
            pa[3] = ph[2 * kk + 1][1];
            mma16816(lacc, pa, ONES2, ONES2);
#pragma unroll
            for (int dtp = 0; dtp < 2; dtp++) {
                uint32_t v0, v1, v2, v3;
                ldsm_x4(v0, v1, v2, v3, &Vs[bf][16 * dtp + rowoff][kk * 16 + coloff]);
                mma16816(o[2 * dtp    ], pa, v0, v1);
                mma16816(o[2 * dtp + 1], pa, v2, v3);
            }
        }
    }

    const float il0 = 1.f / lacc[0];
    const float il1 = 1.f / lacc[2];
#pragma unroll
    for (int dt = 0; dt < 4; dt++) {
#pragma unroll
        for (int j = 0; j < 4; j++) {
            int r = qrow + ((j >> 1) ? 8 : 0);
            int d = dt * 8 + lc + (j & 1);
            float v = o[dt][j] * ((j < 2) ? il0 : il1);
            g_AO[((size_t)b * NN + r) * CC + h * HD + d] = __float2half_rn(v);
        }
    }
}

// -------- launch --------
extern "C" void kernel_launch(void* const* d_in, const int* in_sizes, int n_in,
                              void* d_out, int out_size) {
    const float* x      = (const float*)d_in[0];
    const float* qkv_w  = (const float*)d_in[1];
    const float* qkv_b  = (const float*)d_in[2];
    const float* out_w  = (const float*)d_in[3];
    const float* out_b  = (const float*)d_in[4];
    float* out = (float*)d_out;

    conv_weights<<<TC * CC / 256, 256>>>(qkv_w, out_w);

    dim3 g0(NN / 64, TC / 64, BB);
    gemm_nt<0><<<g0, 128>>>(x, qkv_b, nullptr);

    dim3 gf(NN / 64, HH, BB);
    flash_attn<<<gf, 128>>>();

    dim3 g1(NN / 64, CC / 64, BB);
    gemm_nt<1><<<g1, 128>>>(nullptr, out_b, out);
}

// round 12
// speedup vs baseline: 1.0872x; 1.0866x over previous
#include <cuda_runtime.h>
#include <cuda_fp16.h>
#include <cstdint>
#include <cstddef>

// Problem constants
#define BB 2
#define CC 256
#define NN 4096
#define HH 8
#define HD 32
#define TC 768   // 3*C

// 1/sqrt(32) * log2(e): fold softmax scale + exp2 conversion into Q
__device__ __constant__ float QSCALE_C = 0.17677669529663687f * 1.4426950408889634f;

#define ONES2 0x3C003C00u   // half2(1.0, 1.0)

// -------- scratch (static device globals; no allocation) --------
__device__ __align__(128) __half g_xT  [(size_t)BB * NN * CC];   // [b][n][c]
__device__ __align__(128) __half g_wqkv[(size_t)TC * CC];        // [o][c]
__device__ __align__(128) __half g_wout[(size_t)CC * CC];        // [o][c]
__device__ __align__(128) __half g_Q   [(size_t)BB * HH * NN * HD]; // [b][h][n][d] (pre-scaled)
__device__ __align__(128) __half g_K   [(size_t)BB * HH * NN * HD]; // [b][h][n][d]
__device__ __align__(128) __half g_V   [(size_t)BB * HH * HD * NN]; // [b][h][d][n]
__device__ __align__(128) __half g_AO  [(size_t)BB * NN * CC];   // [b][n][c]

// -------- mma.sync m16n8k16 f16 -> f32 --------
__device__ __forceinline__ void mma16816(float* c, const uint32_t* a, uint32_t b0, uint32_t b1) {
    asm volatile(
        "mma.sync.aligned.m16n8k16.row.col.f32.f16.f16.f32 "
        "{%0,%1,%2,%3}, {%4,%5,%6,%7}, {%8,%9}, {%0,%1,%2,%3};\n"
        : "+f"(c[0]), "+f"(c[1]), "+f"(c[2]), "+f"(c[3])
        : "r"(a[0]), "r"(a[1]), "r"(a[2]), "r"(a[3]), "r"(b0), "r"(b1));
}

__device__ __forceinline__ uint32_t ld_u32s(const __half* p) {
    return *reinterpret_cast<const uint32_t*>(p);
}

__device__ __forceinline__ void ldsm_x4(uint32_t& r0, uint32_t& r1, uint32_t& r2, uint32_t& r3,
                                        const __half* p) {
    uint32_t a = (uint32_t)__cvta_generic_to_shared(p);
    asm volatile("ldmatrix.sync.aligned.m8n8.x4.shared.b16 {%0,%1,%2,%3}, [%4];\n"
                 : "=r"(r0), "=r"(r1), "=r"(r2), "=r"(r3) : "r"(a));
}

__device__ __forceinline__ float ex2f(float x) {
    float y;
    asm("ex2.approx.f32 %0, %1;\n" : "=f"(y) : "f"(x));
    return y;
}

__device__ __forceinline__ uint32_t h2ex2(uint32_t x) {
    uint32_t y;
    asm("ex2.approx.f16x2 %0, %1;\n" : "=r"(y) : "r"(x));
    return y;
}

__device__ __forceinline__ uint32_t pack_h2(float lo, float hi) {
    __half2 t = __floats2half2_rn(lo, hi);
    return *reinterpret_cast<uint32_t*>(&t);
}

__device__ __forceinline__ void cp16(void* dst, const void* src) {
    uint32_t d = (uint32_t)__cvta_generic_to_shared(dst);
    asm volatile("cp.async.cg.shared.global [%0], [%1], 16;\n" :: "r"(d), "l"(src));
}
#define CP_COMMIT asm volatile("cp.async.commit_group;\n" ::: "memory")
#define CP_WAIT0  asm volatile("cp.async.wait_group 0;\n" ::: "memory")

// -------- kernel 1: convert weights to fp16 --------
__global__ void conv_weights(const float* __restrict__ wqkv, const float* __restrict__ wout) {
    int i = blockIdx.x * 256 + threadIdx.x;
    if (i < TC * CC) g_wqkv[i] = __float2half_rn(wqkv[i]);
    if (i < CC * CC) g_wout[i] = __float2half_rn(wout[i]);
}

// -------- kernel 2: transpose x [b][c][n] f32 -> xT [b][n][c] f16 --------
__global__ void transpose_x(const float* __restrict__ x) {
    __shared__ float t[32][33];
    int b  = blockIdx.z;
    int n0 = blockIdx.x * 32;
    int c0 = blockIdx.y * 32;
    int tx = threadIdx.x, ty = threadIdx.y;
#pragma unroll
    for (int j = 0; j < 32; j += 8)
        t[ty + j][tx] = x[((size_t)b * CC + (c0 + ty + j)) * NN + n0 + tx];
    __syncthreads();
#pragma unroll
    for (int j = 0; j < 32; j += 8)
        g_xT[((size_t)b * NN + (n0 + ty + j)) * CC + c0 + tx] = __float2half_rn(t[tx][ty + j]);
}

// -------- kernel 3/5: NT GEMM out[o][n] = sum_c A[o][c] * Bx[n][c] + bias[o] --------
// cp.async double-buffered staging (one barrier per k-tile).
// MODE 0: A = g_wqkv (M=768), Bx = g_xT; epilogue scatters into Q (scaled), K, V.
// MODE 1: A = g_wout (M=256), Bx = g_AO; epilogue writes fp32 d_out [b][o][n].
template <int MODE>
__global__ void __launch_bounds__(128) gemm_nt(const float* __restrict__ bias,
                                              float* __restrict__ outF) {
    __shared__ __half As[2][64][40];
    __shared__ __half Bs[2][64][40];

    const int b  = blockIdx.z;
    const int n0 = blockIdx.x * 64;
    const int o0 = blockIdx.y * 64;
    const int tid   = threadIdx.x;
    const int warp  = tid >> 5;
    const int lane  = tid & 31;
    const int warpM = warp >> 1;
    const int warpN = warp & 1;
    const int lr = lane >> 2;
    const int lc = (lane & 3) * 2;

    const __half* Aw = (MODE == 0) ? g_wqkv : g_wout;
    const __half* Bx = ((MODE == 0) ? g_xT : g_AO) + (size_t)b * NN * CC;

    float acc[2][4][4];
#pragma unroll
    for (int mt = 0; mt < 2; mt++)
#pragma unroll
        for (int nt = 0; nt < 4; nt++)
#pragma unroll
            for (int j = 0; j < 4; j++) acc[mt][nt][j] = 0.f;

    // stage one 64x32 A tile + 64x32 B tile into buffer `buf` via cp.async
    auto stage = [&](int kk0, int buf) {
#pragma unroll
        for (int i = tid; i < 256; i += 128) {
            int row = i >> 2, seg = i & 3;
            cp16(&As[buf][row][seg * 8], &Aw[(size_t)(o0 + row) * CC + kk0 + seg * 8]);
            cp16(&Bs[buf][row][seg * 8], &Bx[(size_t)(n0 + row) * CC + kk0 + seg * 8]);
        }
    };

    const int NIT = CC / 32;   // 8
    stage(0, 0);
    CP_COMMIT;

    for (int it = 0; it < NIT; it++) {
        const int buf = it & 1;
        CP_WAIT0;
        __syncthreads();
        if (it + 1 < NIT) {
            stage((it + 1) * 32, buf ^ 1);
            CP_COMMIT;
        }
#pragma unroll
        for (int ks = 0; ks < 2; ks++) {
            uint32_t a[2][4];
#pragma unroll
            for (int mt = 0; mt < 2; mt++) {
                int r = warpM * 32 + mt * 16 + lr;
                a[mt][0] = ld_u32s(&As[buf][r    ][ks * 16 + lc    ]);
                a[mt][1] = ld_u32s(&As[buf][r + 8][ks * 16 + lc    ]);
                a[mt][2] = ld_u32s(&As[buf][r    ][ks * 16 + lc + 8]);
                a[mt][3] = ld_u32s(&As[buf][r + 8][ks * 16 + lc + 8]);
            }
            uint32_t bf[4][2];
#pragma unroll
            for (int nt = 0; nt < 4; nt++) {
                int c = warpN * 32 + nt * 8 + lr;
                bf[nt][0] = ld_u32s(&Bs[buf][c][ks * 16 + lc    ]);
                bf[nt][1] = ld_u32s(&Bs[buf][c][ks * 16 + lc + 8]);
            }
#pragma unroll
            for (int mt = 0; mt < 2; mt++)
#pragma unroll
                for (int nt = 0; nt < 4; nt++)
                    mma16816(acc[mt][nt], a[mt], bf[nt][0], bf[nt][1]);
        }
    }

    const float qs = QSCALE_C;
#pragma unroll
    for (int mt = 0; mt < 2; mt++) {
#pragma unroll
        for (int nt = 0; nt < 4; nt++) {
#pragma unroll
            for (int j = 0; j < 4; j++) {
                int r_loc = warpM * 32 + mt * 16 + lr + ((j >> 1) ? 8 : 0);
                int c_loc = warpN * 32 + nt * 8 + lc + (j & 1);
                int o = o0 + r_loc;
                int n = n0 + c_loc;
                float v = acc[mt][nt][j] + bias[o];
                if (MODE == 0) {
                    if (o < CC) {
                        int h = o >> 5, d = o & 31;
                        g_Q[(((size_t)b * HH + h) * NN + n) * HD + d] = __float2half_rn(v * qs);
                    } else if (o < 2 * CC) {
                        int o2 = o - CC;
                        int h = o2 >> 5, d = o2 & 31;
                        g_K[(((size_t)b * HH + h) * NN + n) * HD + d] = __float2half_rn(v);
                    } else {
                        int o2 = o - 2 * CC;
                        int h = o2 >> 5, d = o2 & 31;
                        g_V[(((size_t)b * HH + h) * HD + d) * NN + n] = __float2half_rn(v);
                    }
                } else {
                    outF[((size_t)b * CC + o) * NN + n] = v;
                }
            }
        }
    }
}

// -------- kernel 4: flash attention (exact R6 config — best measured) --------
__global__ void __launch_bounds__(128) flash_attn() {
    __shared__ __half Ks[2][64][40];   // [buf][key][d]  80B rows: LDSM conflict-free
    __shared__ __half Vs[2][32][72];   // [buf][d][key]  144B rows: LDSM conflict-free

    const int b  = blockIdx.z;
    const int h  = blockIdx.y;
    const int q0 = blockIdx.x * 64;
    const int tid  = threadIdx.x;
    const int warp = tid >> 5;
    const int lane = tid & 31;
    const int lr = lane >> 2;
    const int lc = (lane & 3) * 2;
    const int lg  = lane >> 3;
    const int lrr = lane & 7;
    const int rowoff = ((lg >> 1) ? 8 : 0) + lrr;
    const int coloff = (lg & 1) * 8;

    const __half* Qb = g_Q + (((size_t)b * HH + h) * NN) * HD;
    const __half* Kb = g_K + (((size_t)b * HH + h) * NN) * HD;
    const __half* Vb = g_V + (((size_t)b * HH + h) * HD) * NN;

    const int qrow = q0 + warp * 16 + lr;

    uint32_t qa[2][4];
#pragma unroll
    for (int ks = 0; ks < 2; ks++) {
        qa[ks][0] = ld_u32s(&Qb[(size_t)(qrow    ) * HD + ks * 16 + lc    ]);
        qa[ks][1] = ld_u32s(&Qb[(size_t)(qrow + 8) * HD + ks * 16 + lc    ]);
        qa[ks][2] = ld_u32s(&Qb[(size_t)(qrow    ) * HD + ks * 16 + lc + 8]);
        qa[ks][3] = ld_u32s(&Qb[(size_t)(qrow + 8) * HD + ks * 16 + lc + 8]);
    }

    float m0 = -1e30f, m1 = -1e30f;
    float o[4][4];
    float lacc[4];
#pragma unroll
    for (int dt = 0; dt < 4; dt++)
#pragma unroll
        for (int j = 0; j < 4; j++) o[dt][j] = 0.f;
#pragma unroll
    for (int j = 0; j < 4; j++) lacc[j] = 0.f;

    auto prefetch = [&](int kt, int bf) {
        const int kn0 = kt * 64;
#pragma unroll
        for (int j = 0; j < 2; j++) {
            int c = tid + j * 128;
            int krow = c >> 2, kseg = c & 3;
            cp16(&Ks[bf][krow][kseg * 8], &Kb[(size_t)(kn0 + krow) * HD + kseg * 8]);
            int vrow = c >> 3, vseg = c & 7;
            cp16(&Vs[bf][vrow][vseg * 8], &Vb[(size_t)vrow * NN + kn0 + vseg * 8]);
        }
    };

    const int NT = NN / 64;
    prefetch(0, 0);
    CP_COMMIT;

    for (int kt = 0; kt < NT; kt++) {
        const int bf = kt & 1;
        CP_WAIT0;
        __syncthreads();
        if (kt + 1 < NT) {
            prefetch(kt + 1, bf ^ 1);
            CP_COMMIT;
        }

        float s[8][4];
#pragma unroll
        for (int nt = 0; nt < 8; nt++)
#pragma unroll
            for (int j = 0; j < 4; j++) s[nt][j] = 0.f;
#pragma unroll
        for (int ks = 0; ks < 2; ks++) {
#pragma unroll
            for (int ntp = 0; ntp < 4; ntp++) {
                uint32_t k0, k1, k2, k3;
                ldsm_x4(k0, k1, k2, k3, &Ks[bf][16 * ntp + rowoff][ks * 16 + coloff]);
                mma16816(s[2 * ntp    ], qa[ks], k0, k1);
                mma16816(s[2 * ntp + 1], qa[ks], k2, k3);
            }
        }

        float mn0 = m0, mn1 = m1;
#pragma unroll
        for (int nt = 0; nt < 8; nt++) {
            mn0 = fmaxf(mn0, fmaxf(s[nt][0], s[nt][1]));
            mn1 = fmaxf(mn1, fmaxf(s[nt][2], s[nt][3]));
        }
#pragma unroll
        for (int off = 1; off < 4; off <<= 1) {
            mn0 = fmaxf(mn0, __shfl_xor_sync(0xffffffffu, mn0, off));
            mn1 = fmaxf(mn1, __shfl_xor_sync(0xffffffffu, mn1, off));
        }

        if (!__all_sync(0xffffffffu, (mn0 == m0) & (mn1 == m1))) {
            const float a0 = ex2f(m0 - mn0);
            const float a1 = ex2f(m1 - mn1);
            m0 = mn0; m1 = mn1;
#pragma unroll
            for (int dt = 0; dt < 4; dt++) {
                o[dt][0] *= a0; o[dt][1] *= a0;
                o[dt][2] *= a1; o[dt][3] *= a1;
            }
            lacc[0] *= a0; lacc[1] *= a0; lacc[2] *= a1; lacc[3] *= a1;
        }

        uint32_t ph[8][2];
#pragma unroll
        for (int nt = 0; nt < 8; nt++) {
            ph[nt][0] = h2ex2(pack_h2(s[nt][0] - m0, s[nt][1] - m0));
            ph[nt][1] = h2ex2(pack_h2(s[nt][2] - m1, s[nt][3] - m1));
        }

#pragma unroll
        for (int kk = 0; kk < 4; kk++) {
            uint32_t pa[4];
            pa[0] = ph[2 * kk    ][0];
            pa[1] = ph[2 * kk    ][1];
            pa[2] = ph[2 * kk + 1][0];
            pa[3] = ph[2 * kk + 1][1];
            mma16816(lacc, pa, ONES2, ONES2);
#pragma unroll
            for (int dtp = 0; dtp < 2; dtp++) {
                uint32_t v0, v1, v2, v3;
                ldsm_x4(v0, v1, v2, v3, &Vs[bf][16 * dtp + rowoff][kk * 16 + coloff]);
                mma16816(o[2 * dtp    ], pa, v0, v1);
                mma16816(o[2 * dtp + 1], pa, v2, v3);
            }
        }
    }

    const float il0 = 1.f / lacc[0];
    const float il1 = 1.f / lacc[2];
#pragma unroll
    for (int dt = 0; dt < 4; dt++) {
#pragma unroll
        for (int j = 0; j < 4; j++) {
            int r = qrow + ((j >> 1) ? 8 : 0);
            int d = dt * 8 + lc + (j & 1);
            float v = o[dt][j] * ((j < 2) ? il0 : il1);
            g_AO[((size_t)b * NN + r) * CC + h * HD + d] = __float2half_rn(v);
        }
    }
}

// -------- launch --------
extern "C" void kernel_launch(void* const* d_in, const int* in_sizes, int n_in,
                              void* d_out, int out_size) {
    const float* x      = (const float*)d_in[0];
    const float* qkv_w  = (const float*)d_in[1];
    const float* qkv_b  = (const float*)d_in[2];
    const float* out_w  = (const float*)d_in[3];
    const float* out_b  = (const float*)d_in[4];
    float* out = (float*)d_out;

    conv_weights<<<TC * CC / 256, 256>>>(qkv_w, out_w);

    dim3 tgrid(NN / 32, CC / 32, BB);
    transpose_x<<<tgrid, dim3(32, 8)>>>(x);

    dim3 g0(NN / 64, TC / 64, BB);
    gemm_nt<0><<<g0, 128>>>(qkv_b, nullptr);

    dim3 gf(NN / 64, HH, BB);
    flash_attn<<<gf, 128>>>();

    dim3 g1(NN / 64, CC / 64, BB);
    gemm_nt<1><<<g1, 128>>>(out_b, out);
}